// round 15
// baseline (speedup 1.0000x reference)
#include <cuda_runtime.h>
#include <math.h>

// Problem constants (fixed by setup_inputs)
#define BB 128
#define TT 32
#define HH 128
#define NNEI 16
#define NHEAD 4
#define LL 544                      // (NNEI+1)*TT
#define CH 8                        // l-chunks
#define CL 68                       // l per chunk (LL/CH)
#define NPAIR 34                    // l-pairs per chunk (CL/2)
#define SCALE 0.08838834764831845f  // 1/sqrt(128)

// Scratch (device globals — no allocations allowed)
__device__ float  g_m[NHEAD * BB * HH];     // m[n][b][h]
__device__ float  g_W2[NHEAD * HH * HH];    // W2[i][e]
__device__ float  g_S[BB * NHEAD * LL];     // raw masked/scaled scores
__device__ float  g_upart[CH * BB * 512];   // chunk u partials (exp-numerator weighted)
__device__ float2 g_MZ[CH * BB * NHEAD];    // chunk (max, sum)
__device__ int    g_cnt[BB];                // finalize counter (zero-init; reset by finalizer)
__device__ int    g_fHigh[4];               // mask-dtype detection votes
__device__ int    g_fMulti[4];

__device__ __forceinline__ float warpRedSum(float v) {
    v += __shfl_xor_sync(0xffffffffu, v, 16);
    v += __shfl_xor_sync(0xffffffffu, v, 8);
    v += __shfl_xor_sync(0xffffffffu, v, 4);
    v += __shfl_xor_sync(0xffffffffu, v, 2);
    v += __shfl_xor_sync(0xffffffffu, v, 1);
    return v;
}
__device__ __forceinline__ float warpRedMax(float v) {
    v = fmaxf(v, __shfl_xor_sync(0xffffffffu, v, 16));
    v = fmaxf(v, __shfl_xor_sync(0xffffffffu, v, 8));
    v = fmaxf(v, __shfl_xor_sync(0xffffffffu, v, 4));
    v = fmaxf(v, __shfl_xor_sync(0xffffffffu, v, 2));
    v = fmaxf(v, __shfl_xor_sync(0xffffffffu, v, 1));
    return v;
}

__device__ __forceinline__ int mask_mode() {
    return (g_fHigh[0] | g_fHigh[1] | g_fHigh[2] | g_fHigh[3]) ? 2
         : ((g_fMulti[0] | g_fMulti[1] | g_fMulti[2] | g_fMulti[3]) ? 1 : 0);
}

// ---------------------------------------------------------------------------
// Kernel 1: prep (132 blocks x 256 threads) — unchanged from R14.
// ---------------------------------------------------------------------------
__global__ __launch_bounds__(256) void prep_kernel(
    const float* __restrict__ node,   // [B,T,H]
    const float* __restrict__ wqs,    // [NH,H,H]
    const float* __restrict__ wks,    // [NH,H,H]
    const float* __restrict__ wvs,    // [NH,H,H]
    const float* __restrict__ prjw,   // [H, NH*H]
    const unsigned int* __restrict__ maskw,
    const int*   __restrict__ stepp)
{
    const int tid = threadIdx.x;
    const int lane = tid & 31;
    const int wid = tid >> 5;

    if (blockIdx.x < 64) {
        __shared__ float q_sm[8 * 128];
        __shared__ float qs_sm[8 * 128];
        const int n  = blockIdx.x >> 4;
        const int b0 = (blockIdx.x & 15) * 8;
        const int ts = stepp[0];

        for (int i = tid; i < 8 * 128; i += 256) {
            int b = i >> 7, h = i & 127;
            q_sm[i] = node[(size_t)(b0 + b) * (TT * HH) + (size_t)ts * HH + h];
        }
        __syncthreads();

        {
            const int d = tid & 127;
            const int bh = (tid >> 7) * 4;
            float a0 = 0.f, a1 = 0.f, a2 = 0.f, a3 = 0.f;
            const float* wq = wqs + (size_t)n * HH * HH + d;
            #pragma unroll 8
            for (int h = 0; h < 128; h++) {
                float w = wq[h * 128];
                a0 += q_sm[(bh + 0) * 128 + h] * w;
                a1 += q_sm[(bh + 1) * 128 + h] * w;
                a2 += q_sm[(bh + 2) * 128 + h] * w;
                a3 += q_sm[(bh + 3) * 128 + h] * w;
            }
            qs_sm[(bh + 0) * 128 + d] = a0;
            qs_sm[(bh + 1) * 128 + d] = a1;
            qs_sm[(bh + 2) * 128 + d] = a2;
            qs_sm[(bh + 3) * 128 + d] = a3;
        }
        __syncthreads();

        {
            const int half = lane >> 4;
            const int j = lane & 15;
            #pragma unroll 1
            for (int p = wid; p < 64; p += 8) {
                int h = p * 2 + half;
                const float* wkr = wks + (size_t)n * HH * HH + (size_t)h * 128;
                float4 wa = *reinterpret_cast<const float4*>(wkr + j * 4);
                float4 wb = *reinterpret_cast<const float4*>(wkr + 64 + j * 4);
                #pragma unroll
                for (int bb = 0; bb < 8; bb++) {
                    float4 qa = *reinterpret_cast<const float4*>(qs_sm + bb * 128 + j * 4);
                    float4 qb = *reinterpret_cast<const float4*>(qs_sm + bb * 128 + 64 + j * 4);
                    float s = wa.x*qa.x + wa.y*qa.y + wa.z*qa.z + wa.w*qa.w
                            + wb.x*qb.x + wb.y*qb.y + wb.z*qb.z + wb.w*qb.w;
                    s += __shfl_xor_sync(0xffffffffu, s, 1);
                    s += __shfl_xor_sync(0xffffffffu, s, 2);
                    s += __shfl_xor_sync(0xffffffffu, s, 4);
                    s += __shfl_xor_sync(0xffffffffu, s, 8);
                    if (j == 0)
                        g_m[((size_t)n * 128 + b0 + bb) * 128 + h] = s;
                }
            }
        }
    } else if (blockIdx.x < 128) {
        __shared__ float wv_sm[8 * 132];
        __shared__ float p_sm[32 * 132];
        const int jb = blockIdx.x - 64;
        const int n  = jb >> 4;
        const int h0 = (jb & 15) * 8;

        for (int i = tid; i < 8 * 128; i += 256) {
            int k = i >> 7, d = i & 127;
            wv_sm[k * 132 + d] = wvs[(size_t)n * HH * HH + (size_t)(h0 + k) * 128 + d];
        }

        const int e_l = tid >> 3;
        const int k   = tid & 7;
        const float4* wv4 = reinterpret_cast<const float4*>(wv_sm + k * 132);

        #pragma unroll 1
        for (int ec = 0; ec < 4; ec++) {
            __syncthreads();
            for (int i = tid; i < 32 * 128; i += 256) {
                int e = i >> 7, d = i & 127;
                p_sm[e * 132 + d] = prjw[(size_t)(ec * 32 + e) * (NHEAD * HH) + n * 128 + d];
            }
            __syncthreads();

            const float4* pe4 = reinterpret_cast<const float4*>(p_sm + e_l * 132);
            float a = 0.f;
            #pragma unroll 8
            for (int d4 = 0; d4 < 32; d4++) {
                float4 w = wv4[d4];
                float4 p = pe4[d4];
                a += w.x*p.x + w.y*p.y + w.z*p.z + w.w*p.w;
            }
            g_W2[((size_t)n * 128 + h0 + k) * 128 + (ec * 32 + e_l)] = a;
        }
    } else {
        __shared__ int sH, sM;
        if (tid == 0) { sH = 0; sM = 0; }
        __syncthreads();
        const int q = blockIdx.x - 128;
        const int QW = (BB * LL / 4) / 4;
        const unsigned int* p = maskw + q * QW;
        int lh = 0, lm = 0;
        #pragma unroll 4
        for (int i = tid; i < QW; i += 256) {
            unsigned int w = p[i];
            unsigned int b0 = w & 0xFFu, b1 = (w >> 8) & 0xFFu,
                         b2 = (w >> 16) & 0xFFu, b3 = (w >> 24) & 0xFFu;
            if (b0 > 1u || b1 > 1u || b2 > 1u || b3 > 1u) lh = 1;
            if ((w & 0xFFFFFF00u) != 0u) lm = 1;
        }
        if (lh) atomicOr(&sH, 1);
        if (lm) atomicOr(&sM, 1);
        __syncthreads();
        if (tid == 0) { g_fHigh[q] = sH; g_fMulti[q] = sM; }
    }
}

// ---------------------------------------------------------------------------
// Kernel 2: mega2 v2. grid (128 b, 8 c) x 256 threads.
// ---------------------------------------------------------------------------
__global__ __launch_bounds__(256, 4) void mega2_kernel(
    const float* __restrict__ node,    // [B,T,H]
    const float* __restrict__ neigh,   // [B,N*T,H]
    const void*  __restrict__ maskraw, // [B,L]
    const float* __restrict__ prjb,
    const float* __restrict__ gamma,
    const float* __restrict__ beta,
    const int*   __restrict__ stepp,
    float* __restrict__ outp)
{
    __shared__ float kv_sm[CL * 128];   // 34 KB (reused for combine + finalize)
    __shared__ float m_sm[NHEAD * HH];  // 2 KB
    __shared__ float SS[NHEAD * CL];    // scores -> exp numerators
    __shared__ float sCoef[NHEAD * CH];
    __shared__ float sMg[NHEAD];
    __shared__ float sZinv[NHEAD];
    __shared__ float red[8], red2[8];
    __shared__ int   isLast;

    const int tid = threadIdx.x;
    const int b = blockIdx.x;
    const int c = blockIdx.y;
    const int lane = tid & 31;
    const int wid = tid >> 5;
    const int j = lane & 15;
    const int half = lane >> 4;
    const float NEG_INF = __int_as_float(0xff800000u);
    const int l0 = c * CL;

    // m for this b
    m_sm[tid]       = g_m[((size_t)(tid >> 7) * 128 + b) * 128 + (tid & 127)];
    m_sm[tid + 256] = g_m[((size_t)((tid + 256) >> 7) * 128 + b) * 128 + ((tid + 256) & 127)];

    // stage kv chunk
    const float4* nodeB  = reinterpret_cast<const float4*>(node  + (size_t)b * TT * HH);
    const float4* neighB = reinterpret_cast<const float4*>(neigh + (size_t)b * NNEI * TT * HH);
    {
        float4* kv4s = reinterpret_cast<float4*>(kv_sm);
        for (int i = tid; i < CL * 32; i += 256) {
            int row = i >> 5, f4 = i & 31;
            int l = l0 + row;
            kv4s[i] = (l < TT) ? nodeB[(size_t)l * 32 + f4] : neighB[(size_t)(l - TT) * 32 + f4];
        }
    }
    __syncthreads();

    // ---- scores from smem: 2 pairs per step (ILP across shuffle chains) ----
    {
        const int mode = mask_mode();
        const float4* m4 = reinterpret_cast<const float4*>(m_sm);
        const float4* kv4 = reinterpret_cast<const float4*>(kv_sm);

        #pragma unroll
        for (int t = 0; t < 2; t++) {
            int pA = wid + t * 16;
            int pB = pA + 8;
            int llA = 2 * pA + half, llB = 2 * pB + half;
            float4 vA0 = kv4[llA * 32 + j];
            float4 vA1 = kv4[llA * 32 + 16 + j];
            float4 vB0 = kv4[llB * 32 + j];
            float4 vB1 = kv4[llB * 32 + 16 + j];
            float sA[4], sB[4];
            #pragma unroll
            for (int n = 0; n < 4; n++) {
                float4 ma = m4[n * 32 + j];
                float4 mb = m4[n * 32 + 16 + j];
                sA[n] = vA0.x*ma.x + vA0.y*ma.y + vA0.z*ma.z + vA0.w*ma.w
                      + vA1.x*mb.x + vA1.y*mb.y + vA1.z*mb.z + vA1.w*mb.w;
                sB[n] = vB0.x*ma.x + vB0.y*ma.y + vB0.z*ma.z + vB0.w*ma.w
                      + vB1.x*mb.x + vB1.y*mb.y + vB1.z*mb.z + vB1.w*mb.w;
            }
            #pragma unroll
            for (int n = 0; n < 4; n++) {
                sA[n] += __shfl_xor_sync(0xffffffffu, sA[n], 1);
                sB[n] += __shfl_xor_sync(0xffffffffu, sB[n], 1);
            }
            #pragma unroll
            for (int n = 0; n < 4; n++) {
                sA[n] += __shfl_xor_sync(0xffffffffu, sA[n], 2);
                sB[n] += __shfl_xor_sync(0xffffffffu, sB[n], 2);
            }
            int q = lane & 3;
            float wA = (q == 0) ? sA[0] : (q == 1) ? sA[1] : (q == 2) ? sA[2] : sA[3];
            float wB = (q == 0) ? sB[0] : (q == 1) ? sB[1] : (q == 2) ? sB[2] : sB[3];
            wA += __shfl_xor_sync(0xffffffffu, wA, 4);
            wB += __shfl_xor_sync(0xffffffffu, wB, 4);
            wA += __shfl_xor_sync(0xffffffffu, wA, 8);
            wB += __shfl_xor_sync(0xffffffffu, wB, 8);
            if ((lane & 12) == 0) {
                size_t miA = (size_t)b * LL + l0 + llA;
                size_t miB = (size_t)b * LL + l0 + llB;
                bool mkA, mkB;
                if (mode == 0) {
                    mkA = (reinterpret_cast<const int*>(maskraw)[miA] != 0);
                    mkB = (reinterpret_cast<const int*>(maskraw)[miB] != 0);
                } else if (mode == 1) {
                    mkA = (reinterpret_cast<const unsigned char*>(maskraw)[miA] != 0);
                    mkB = (reinterpret_cast<const unsigned char*>(maskraw)[miB] != 0);
                } else {
                    mkA = (reinterpret_cast<const float*>(maskraw)[miA] != 0.f);
                    mkB = (reinterpret_cast<const float*>(maskraw)[miB] != 0.f);
                }
                float svA = mkA ? NEG_INF : wA * SCALE;
                float svB = mkB ? NEG_INF : wB * SCALE;
                SS[q * CL + llA] = svA;
                SS[q * CL + llB] = svB;
                g_S[((size_t)b * NHEAD + q) * LL + l0 + llA] = svA;
                g_S[((size_t)b * NHEAD + q) * LL + l0 + llB] = svB;
            }
        }
        // remainder pairs 32, 33 (warps 0, 1)
        if (wid < 2) {
            int p = 32 + wid;
            int ll = 2 * p + half;
            float4 v0 = kv4[ll * 32 + j];
            float4 v1 = kv4[ll * 32 + 16 + j];
            float s[4];
            #pragma unroll
            for (int n = 0; n < 4; n++) {
                float4 ma = m4[n * 32 + j];
                float4 mb = m4[n * 32 + 16 + j];
                s[n] = v0.x*ma.x + v0.y*ma.y + v0.z*ma.z + v0.w*ma.w
                     + v1.x*mb.x + v1.y*mb.y + v1.z*mb.z + v1.w*mb.w;
            }
            #pragma unroll
            for (int n = 0; n < 4; n++) {
                s[n] += __shfl_xor_sync(0xffffffffu, s[n], 1);
                s[n] += __shfl_xor_sync(0xffffffffu, s[n], 2);
            }
            int q = lane & 3;
            float w = (q == 0) ? s[0] : (q == 1) ? s[1] : (q == 2) ? s[2] : s[3];
            w += __shfl_xor_sync(0xffffffffu, w, 4);
            w += __shfl_xor_sync(0xffffffffu, w, 8);
            if ((lane & 12) == 0) {
                size_t mi = (size_t)b * LL + l0 + ll;
                bool mk;
                if (mode == 0)      mk = (reinterpret_cast<const int*>(maskraw)[mi] != 0);
                else if (mode == 1) mk = (reinterpret_cast<const unsigned char*>(maskraw)[mi] != 0);
                else                mk = (reinterpret_cast<const float*>(maskraw)[mi] != 0.f);
                float sv = mk ? NEG_INF : w * SCALE;
                SS[q * CL + ll] = sv;
                g_S[((size_t)b * NHEAD + q) * LL + l0 + ll] = sv;
            }
        }
    }
    __syncthreads();

    // ---- chunk softmax stats (warp n handles head n) ----
    if (wid < 4) {
        const int n = wid;
        float v0 = SS[n * CL + lane];
        float v1 = SS[n * CL + 32 + lane];
        float v2 = (lane < 4) ? SS[n * CL + 64 + lane] : NEG_INF;
        float M = warpRedMax(fmaxf(fmaxf(v0, v1), v2));
        float Mu = fmaxf(M, -1e30f);
        float e0 = __expf(v0 - Mu);
        float e1 = __expf(v1 - Mu);
        float e2 = (lane < 4) ? __expf(v2 - Mu) : 0.f;
        float Z = warpRedSum(e0 + e1 + e2);
        SS[n * CL + lane] = e0;
        SS[n * CL + 32 + lane] = e1;
        if (lane < 4) SS[n * CL + 64 + lane] = e2;
        if (lane == 0)
            g_MZ[((size_t)c * BB + b) * NHEAD + n] = make_float2(M, Z);
    }
    __syncthreads();

    // ---- u-partials (float4): warp w -> (n = w>>1, l-half = w&1), lane -> h4 ----
    {
        const int n  = wid >> 1;
        const int lh = wid & 1;
        const float4* kv4 = reinterpret_cast<const float4*>(kv_sm);
        float4 acc = make_float4(0.f, 0.f, 0.f, 0.f);
        const int lb = lh * 34;
        #pragma unroll 2
        for (int i = 0; i < 34; i++) {
            int l = lb + i;
            float4 kvv = kv4[l * 32 + lane];
            float ss = SS[n * CL + l];          // warp-uniform broadcast
            acc.x += ss * kvv.x; acc.y += ss * kvv.y;
            acc.z += ss * kvv.z; acc.w += ss * kvv.w;
        }
        __syncthreads();                        // kv_sm free now
        float4* comb = reinterpret_cast<float4*>(kv_sm);
        comb[tid] = acc;                        // [n][lh][h4]
        __syncthreads();
        if (tid < 128) {
            int nn = tid >> 5, hh = tid & 31;
            float4 a = comb[nn * 64 + hh];
            float4 bq = comb[nn * 64 + 32 + hh];
            a.x += bq.x; a.y += bq.y; a.z += bq.z; a.w += bq.w;
            reinterpret_cast<float4*>(g_upart + ((size_t)c * BB + b) * 512)[nn * 32 + hh] = a;
        }
    }

    // ---- last block per b finalizes ----
    __threadfence();
    __syncthreads();
    if (tid == 0) isLast = (atomicAdd(&g_cnt[b], 1) == CH - 1);
    __syncthreads();
    if (!isLast) return;
    __threadfence();

    // combine chunk stats: warp n handles head n; lanes 0..7 = chunks
    if (wid < 4) {
        const int n = wid;
        float Mc = NEG_INF, Zc = 0.f;
        if (lane < CH) {
            float2 mz = g_MZ[((size_t)lane * BB + b) * NHEAD + n];
            Mc = mz.x; Zc = mz.y;
        }
        float M = warpRedMax(Mc);
        float wgt = (lane < CH) ? Zc * __expf(Mc - M) : 0.f;
        float Z = warpRedSum(wgt);
        if (lane < CH) sCoef[n * CH + lane] = __expf(Mc - M) / Z;
        if (lane == 0) { sMg[n] = M; sZinv[n] = 1.f / Z; }
    }
    __syncthreads();

    float* u_sm = kv_sm;
    float* part = kv_sm + 512;
    #pragma unroll
    for (int r = 0; r < 2; r++) {
        int idx = tid + r * 256;
        int n = idx >> 7;
        float u = 0.f;
        #pragma unroll
        for (int cc = 0; cc < CH; cc++)
            u += g_upart[((size_t)cc * BB + b) * 512 + idx] * sCoef[n * CH + cc];
        u_sm[idx] = u;
    }
    __syncthreads();

    // projection: warp wid handles i in [wid*64, wid*64+64); lane owns float4 of e
    {
        const float4* W24 = reinterpret_cast<const float4*>(g_W2);
        float4 acc = make_float4(0, 0, 0, 0);
        const int i0 = wid * 64;
        #pragma unroll 8
        for (int k = 0; k < 64; k++) {
            int i = i0 + k;
            float uv = u_sm[i];
            float4 wv = W24[(size_t)i * 32 + lane];
            acc.x += uv * wv.x; acc.y += uv * wv.y; acc.z += uv * wv.z; acc.w += uv * wv.w;
        }
        reinterpret_cast<float4*>(part)[wid * 32 + lane] = acc;
    }
    __syncthreads();

    // residual + LayerNorm
    {
        const int ts = stepp[0];
        float x = 0.f;
        if (tid < 128) {
            float p = 0.f;
            #pragma unroll
            for (int w = 0; w < 8; w++) p += part[w * 128 + tid];
            x = p + prjb[tid] + node[(size_t)b * (TT * HH) + (size_t)ts * HH + tid];
        }
        float ws = warpRedSum(x);
        if (tid < 128 && lane == 0) red[wid] = ws;
        __syncthreads();
        float mean = (red[0] + red[1] + red[2] + red[3]) * (1.f / 128.f);
        float d = x - mean;
        float wq = warpRedSum(d * d);
        if (tid < 128 && lane == 0) red2[wid] = wq;
        __syncthreads();
        if (tid < 128) {
            float var = (red2[0] + red2[1] + red2[2] + red2[3]) * (1.f / 128.f);
            outp[(size_t)b * 128 + tid] = d * rsqrtf(var + 1e-6f) * gamma[tid] + beta[tid];
        }
    }

    // slf_attn for the whole row b
    {
        const float* Sb = g_S + (size_t)b * NHEAD * LL;
        for (int l = tid; l < LL; l += 256) {
            float s = __expf(Sb[0 * LL + l] - sMg[0]) * sZinv[0]
                    + __expf(Sb[1 * LL + l] - sMg[1]) * sZinv[1]
                    + __expf(Sb[2 * LL + l] - sMg[2]) * sZinv[2]
                    + __expf(Sb[3 * LL + l] - sMg[3]) * sZinv[3];
            outp[BB * HH + (size_t)b * LL + l] = s;
        }
        if (tid == 0) g_cnt[b] = 0;   // reset for next graph replay
    }
}

extern "C" void kernel_launch(void* const* d_in, const int* in_sizes, int n_in,
                              void* d_out, int out_size)
{
    const float* node  = (const float*)d_in[0];
    const float* neigh = (const float*)d_in[1];
    const void*  mask  = d_in[2];
    const int*   step  = (const int*)d_in[3];
    const float* wqs   = (const float*)d_in[4];
    const float* wks   = (const float*)d_in[5];
    const float* wvs   = (const float*)d_in[6];
    const float* prjw  = (const float*)d_in[7];
    const float* prjb  = (const float*)d_in[8];
    const float* gamma = (const float*)d_in[9];
    const float* beta  = (const float*)d_in[10];
    float* outp = (float*)d_out;

    prep_kernel<<<132, 256>>>(node, wqs, wks, wvs, prjw,
                              (const unsigned int*)mask, step);
    mega2_kernel<<<dim3(BB, CH), 256>>>(node, neigh, mask, prjb, gamma, beta,
                                        step, outp);
}

// round 16
// speedup vs baseline: 1.0089x; 1.0089x over previous
#include <cuda_runtime.h>
#include <math.h>

// Problem constants (fixed by setup_inputs)
#define BB 128
#define TT 32
#define HH 128
#define NNEI 16
#define NHEAD 4
#define LL 544                      // (NNEI+1)*TT
#define CH 8                        // l-chunks
#define CL 68                       // l per chunk (LL/CH)
#define NPAIR 34                    // l-pairs per chunk (CL/2)
#define SCALE 0.08838834764831845f  // 1/sqrt(128)

// Scratch (device globals — no allocations allowed)
__device__ float  g_m[NHEAD * BB * HH];     // m[n][b][h]
__device__ float  g_W2[NHEAD * HH * HH];    // W2[i][e]
__device__ float  g_S[BB * NHEAD * LL];     // raw masked/scaled scores
__device__ float  g_upart[CH * BB * 512];   // chunk u partials
__device__ float2 g_MZ[CH * BB * NHEAD];    // chunk (max, sum)
__device__ int    g_cnt[BB];                // finalize counter
__device__ int    g_fHigh[4];               // mask-dtype detection votes
__device__ int    g_fMulti[4];

__device__ __forceinline__ float warpRedSum(float v) {
    v += __shfl_xor_sync(0xffffffffu, v, 16);
    v += __shfl_xor_sync(0xffffffffu, v, 8);
    v += __shfl_xor_sync(0xffffffffu, v, 4);
    v += __shfl_xor_sync(0xffffffffu, v, 2);
    v += __shfl_xor_sync(0xffffffffu, v, 1);
    return v;
}
__device__ __forceinline__ float warpRedMax(float v) {
    v = fmaxf(v, __shfl_xor_sync(0xffffffffu, v, 16));
    v = fmaxf(v, __shfl_xor_sync(0xffffffffu, v, 8));
    v = fmaxf(v, __shfl_xor_sync(0xffffffffu, v, 4));
    v = fmaxf(v, __shfl_xor_sync(0xffffffffu, v, 2));
    v = fmaxf(v, __shfl_xor_sync(0xffffffffu, v, 1));
    return v;
}

__device__ __forceinline__ int mask_mode() {
    return (g_fHigh[0] | g_fHigh[1] | g_fHigh[2] | g_fHigh[3]) ? 2
         : ((g_fMulti[0] | g_fMulti[1] | g_fMulti[2] | g_fMulti[3]) ? 1 : 0);
}

// ---------------------------------------------------------------------------
// Kernel 1: prep (132 blocks x 256 threads) — unchanged from R14.
// ---------------------------------------------------------------------------
__global__ __launch_bounds__(256) void prep_kernel(
    const float* __restrict__ node,   // [B,T,H]
    const float* __restrict__ wqs,    // [NH,H,H]
    const float* __restrict__ wks,    // [NH,H,H]
    const float* __restrict__ wvs,    // [NH,H,H]
    const float* __restrict__ prjw,   // [H, NH*H]
    const unsigned int* __restrict__ maskw,
    const int*   __restrict__ stepp)
{
    const int tid = threadIdx.x;
    const int lane = tid & 31;
    const int wid = tid >> 5;

    if (blockIdx.x < 64) {
        __shared__ float q_sm[8 * 128];
        __shared__ float qs_sm[8 * 128];
        const int n  = blockIdx.x >> 4;
        const int b0 = (blockIdx.x & 15) * 8;
        const int ts = stepp[0];

        for (int i = tid; i < 8 * 128; i += 256) {
            int b = i >> 7, h = i & 127;
            q_sm[i] = node[(size_t)(b0 + b) * (TT * HH) + (size_t)ts * HH + h];
        }
        __syncthreads();

        {
            const int d = tid & 127;
            const int bh = (tid >> 7) * 4;
            float a0 = 0.f, a1 = 0.f, a2 = 0.f, a3 = 0.f;
            const float* wq = wqs + (size_t)n * HH * HH + d;
            #pragma unroll 8
            for (int h = 0; h < 128; h++) {
                float w = wq[h * 128];
                a0 += q_sm[(bh + 0) * 128 + h] * w;
                a1 += q_sm[(bh + 1) * 128 + h] * w;
                a2 += q_sm[(bh + 2) * 128 + h] * w;
                a3 += q_sm[(bh + 3) * 128 + h] * w;
            }
            qs_sm[(bh + 0) * 128 + d] = a0;
            qs_sm[(bh + 1) * 128 + d] = a1;
            qs_sm[(bh + 2) * 128 + d] = a2;
            qs_sm[(bh + 3) * 128 + d] = a3;
        }
        __syncthreads();

        {
            const int half = lane >> 4;
            const int j = lane & 15;
            #pragma unroll 1
            for (int p = wid; p < 64; p += 8) {
                int h = p * 2 + half;
                const float* wkr = wks + (size_t)n * HH * HH + (size_t)h * 128;
                float4 wa = *reinterpret_cast<const float4*>(wkr + j * 4);
                float4 wb = *reinterpret_cast<const float4*>(wkr + 64 + j * 4);
                #pragma unroll
                for (int bb = 0; bb < 8; bb++) {
                    float4 qa = *reinterpret_cast<const float4*>(qs_sm + bb * 128 + j * 4);
                    float4 qb = *reinterpret_cast<const float4*>(qs_sm + bb * 128 + 64 + j * 4);
                    float s = wa.x*qa.x + wa.y*qa.y + wa.z*qa.z + wa.w*qa.w
                            + wb.x*qb.x + wb.y*qb.y + wb.z*qb.z + wb.w*qb.w;
                    s += __shfl_xor_sync(0xffffffffu, s, 1);
                    s += __shfl_xor_sync(0xffffffffu, s, 2);
                    s += __shfl_xor_sync(0xffffffffu, s, 4);
                    s += __shfl_xor_sync(0xffffffffu, s, 8);
                    if (j == 0)
                        g_m[((size_t)n * 128 + b0 + bb) * 128 + h] = s;
                }
            }
        }
    } else if (blockIdx.x < 128) {
        __shared__ float wv_sm[8 * 132];
        __shared__ float p_sm[32 * 132];
        const int jb = blockIdx.x - 64;
        const int n  = jb >> 4;
        const int h0 = (jb & 15) * 8;

        for (int i = tid; i < 8 * 128; i += 256) {
            int k = i >> 7, d = i & 127;
            wv_sm[k * 132 + d] = wvs[(size_t)n * HH * HH + (size_t)(h0 + k) * 128 + d];
        }

        const int e_l = tid >> 3;
        const int k   = tid & 7;
        const float4* wv4 = reinterpret_cast<const float4*>(wv_sm + k * 132);

        #pragma unroll 1
        for (int ec = 0; ec < 4; ec++) {
            __syncthreads();
            for (int i = tid; i < 32 * 128; i += 256) {
                int e = i >> 7, d = i & 127;
                p_sm[e * 132 + d] = prjw[(size_t)(ec * 32 + e) * (NHEAD * HH) + n * 128 + d];
            }
            __syncthreads();

            const float4* pe4 = reinterpret_cast<const float4*>(p_sm + e_l * 132);
            float a = 0.f;
            #pragma unroll 8
            for (int d4 = 0; d4 < 32; d4++) {
                float4 w = wv4[d4];
                float4 p = pe4[d4];
                a += w.x*p.x + w.y*p.y + w.z*p.z + w.w*p.w;
            }
            g_W2[((size_t)n * 128 + h0 + k) * 128 + (ec * 32 + e_l)] = a;
        }
    } else {
        __shared__ int sH, sM;
        if (tid == 0) { sH = 0; sM = 0; }
        __syncthreads();
        const int q = blockIdx.x - 128;
        const int QW = (BB * LL / 4) / 4;
        const unsigned int* p = maskw + q * QW;
        int lh = 0, lm = 0;
        #pragma unroll 4
        for (int i = tid; i < QW; i += 256) {
            unsigned int w = p[i];
            unsigned int b0 = w & 0xFFu, b1 = (w >> 8) & 0xFFu,
                         b2 = (w >> 16) & 0xFFu, b3 = (w >> 24) & 0xFFu;
            if (b0 > 1u || b1 > 1u || b2 > 1u || b3 > 1u) lh = 1;
            if ((w & 0xFFFFFF00u) != 0u) lm = 1;
        }
        if (lh) atomicOr(&sH, 1);
        if (lm) atomicOr(&sM, 1);
        __syncthreads();
        if (tid == 0) { g_fHigh[q] = sH; g_fMulti[q] = sM; }
    }
}

// ---------------------------------------------------------------------------
// Kernel 2: mega2 v3. grid (128 b, 8 c) x 256 threads, 5 blocks/SM.
// ---------------------------------------------------------------------------
__global__ __launch_bounds__(256, 5) void mega2_kernel(
    const float* __restrict__ node,    // [B,T,H]
    const float* __restrict__ neigh,   // [B,N*T,H]
    const void*  __restrict__ maskraw, // [B,L]
    const float* __restrict__ prjb,
    const float* __restrict__ gamma,
    const float* __restrict__ beta,
    const int*   __restrict__ stepp,
    float* __restrict__ outp)
{
    __shared__ float kv_sm[CL * 128];   // 34 KB (reused for combine + finalize)
    __shared__ float m_sm[NHEAD * HH];  // 2 KB
    __shared__ float SS[NHEAD * CL];    // scores -> exp numerators
    __shared__ float sCoef[NHEAD * CH];
    __shared__ float sMg[NHEAD];
    __shared__ float sZinv[NHEAD];
    __shared__ float red[8], red2[8];
    __shared__ int   isLast;

    const int tid = threadIdx.x;
    const int b = blockIdx.x;
    const int c = blockIdx.y;
    const int lane = tid & 31;
    const int wid = tid >> 5;
    const int j = lane & 15;
    const int half = lane >> 4;
    const float NEG_INF = __int_as_float(0xff800000u);
    const int l0 = c * CL;

    // m for this b
    m_sm[tid]       = g_m[((size_t)(tid >> 7) * 128 + b) * 128 + (tid & 127)];
    m_sm[tid + 256] = g_m[((size_t)((tid + 256) >> 7) * 128 + b) * 128 + ((tid + 256) & 127)];

    // ---- stage kv chunk (specialized: c==0 mixed, c>0 pure-neighbor linear) ----
    {
        float4* kv4s = reinterpret_cast<float4*>(kv_sm);
        if (c == 0) {
            const float4* nodeB  = reinterpret_cast<const float4*>(node  + (size_t)b * TT * HH);
            const float4* neighB = reinterpret_cast<const float4*>(neigh + (size_t)b * NNEI * TT * HH);
            for (int i = tid; i < CL * 32; i += 256) {
                int row = i >> 5, f4 = i & 31;
                kv4s[i] = (row < TT) ? nodeB[row * 32 + f4] : neighB[(row - TT) * 32 + f4];
            }
        } else {
            const float4* src = reinterpret_cast<const float4*>(
                neigh + (size_t)b * NNEI * TT * HH) + (size_t)(l0 - TT) * 32;
            #pragma unroll
            for (int r = 0; r < 8; r++)
                kv4s[tid + r * 256] = src[tid + r * 256];
            if (tid < 128)
                kv4s[2048 + tid] = src[2048 + tid];   // 2176 total
        }
    }
    __syncthreads();

    // ---- scores from smem: 4 unrolled pairs + remainder ----
    {
        const int mode = mask_mode();
        const float4* m4 = reinterpret_cast<const float4*>(m_sm);
        const float4* kv4 = reinterpret_cast<const float4*>(kv_sm);
        float* gSb = g_S + (size_t)b * NHEAD * LL + l0;

        #pragma unroll
        for (int t = 0; t < 4; t++) {
            const int ll = 2 * (wid + t * 8) + half;
            float4 v0 = kv4[ll * 32 + j];
            float4 v1 = kv4[ll * 32 + 16 + j];
            float s[4];
            #pragma unroll
            for (int n = 0; n < 4; n++) {
                float4 ma = m4[n * 32 + j];
                float4 mb = m4[n * 32 + 16 + j];
                s[n] = v0.x*ma.x + v0.y*ma.y + v0.z*ma.z + v0.w*ma.w
                     + v1.x*mb.x + v1.y*mb.y + v1.z*mb.z + v1.w*mb.w;
            }
            #pragma unroll
            for (int n = 0; n < 4; n++) {
                s[n] += __shfl_xor_sync(0xffffffffu, s[n], 1);
                s[n] += __shfl_xor_sync(0xffffffffu, s[n], 2);
            }
            int q = lane & 3;
            float w = (q == 0) ? s[0] : (q == 1) ? s[1] : (q == 2) ? s[2] : s[3];
            w += __shfl_xor_sync(0xffffffffu, w, 4);
            w += __shfl_xor_sync(0xffffffffu, w, 8);
            if ((lane & 12) == 0) {
                bool mk;
                size_t mi = (size_t)b * LL + l0 + ll;
                if (mode == 0)      mk = (reinterpret_cast<const int*>(maskraw)[mi] != 0);
                else if (mode == 1) mk = (reinterpret_cast<const unsigned char*>(maskraw)[mi] != 0);
                else                mk = (reinterpret_cast<const float*>(maskraw)[mi] != 0.f);
                float sv = mk ? NEG_INF : w * SCALE;
                SS[q * CL + ll] = sv;
                gSb[q * LL + ll] = sv;
            }
        }
        // remainder pairs 32, 33 (warps 0, 1)
        if (wid < 2) {
            const int ll = 2 * (32 + wid) + half;
            float4 v0 = kv4[ll * 32 + j];
            float4 v1 = kv4[ll * 32 + 16 + j];
            float s[4];
            #pragma unroll
            for (int n = 0; n < 4; n++) {
                float4 ma = m4[n * 32 + j];
                float4 mb = m4[n * 32 + 16 + j];
                s[n] = v0.x*ma.x + v0.y*ma.y + v0.z*ma.z + v0.w*ma.w
                     + v1.x*mb.x + v1.y*mb.y + v1.z*mb.z + v1.w*mb.w;
            }
            #pragma unroll
            for (int n = 0; n < 4; n++) {
                s[n] += __shfl_xor_sync(0xffffffffu, s[n], 1);
                s[n] += __shfl_xor_sync(0xffffffffu, s[n], 2);
            }
            int q = lane & 3;
            float w = (q == 0) ? s[0] : (q == 1) ? s[1] : (q == 2) ? s[2] : s[3];
            w += __shfl_xor_sync(0xffffffffu, w, 4);
            w += __shfl_xor_sync(0xffffffffu, w, 8);
            if ((lane & 12) == 0) {
                bool mk;
                size_t mi = (size_t)b * LL + l0 + ll;
                if (mode == 0)      mk = (reinterpret_cast<const int*>(maskraw)[mi] != 0);
                else if (mode == 1) mk = (reinterpret_cast<const unsigned char*>(maskraw)[mi] != 0);
                else                mk = (reinterpret_cast<const float*>(maskraw)[mi] != 0.f);
                float sv = mk ? NEG_INF : w * SCALE;
                SS[q * CL + ll] = sv;
                gSb[q * LL + ll] = sv;
            }
        }
    }
    __syncthreads();

    // ---- chunk softmax stats (warp n handles head n) ----
    if (wid < 4) {
        const int n = wid;
        float v0 = SS[n * CL + lane];
        float v1 = SS[n * CL + 32 + lane];
        float v2 = (lane < 4) ? SS[n * CL + 64 + lane] : NEG_INF;
        float M = warpRedMax(fmaxf(fmaxf(v0, v1), v2));
        float Mu = fmaxf(M, -1e30f);
        float e0 = __expf(v0 - Mu);
        float e1 = __expf(v1 - Mu);
        float e2 = (lane < 4) ? __expf(v2 - Mu) : 0.f;
        float Z = warpRedSum(e0 + e1 + e2);
        SS[n * CL + lane] = e0;
        SS[n * CL + 32 + lane] = e1;
        if (lane < 4) SS[n * CL + 64 + lane] = e2;
        if (lane == 0)
            g_MZ[((size_t)c * BB + b) * NHEAD + n] = make_float2(M, Z);
    }
    __syncthreads();

    // ---- u-partials (float4, FULL unroll): warp -> (n = w>>1, l-half = w&1) ----
    {
        const int n  = wid >> 1;
        const int lh = wid & 1;
        const float4* kvb = reinterpret_cast<const float4*>(kv_sm) + lh * 34 * 32 + lane;
        const float*  ssb = SS + n * CL + lh * 34;
        float4 acc = make_float4(0.f, 0.f, 0.f, 0.f);
        #pragma unroll
        for (int i = 0; i < 34; i++) {
            float4 kvv = kvb[i * 32];
            float ss = ssb[i];          // warp-uniform broadcast
            acc.x += ss * kvv.x; acc.y += ss * kvv.y;
            acc.z += ss * kvv.z; acc.w += ss * kvv.w;
        }
        __syncthreads();                // all reads of kv_sm done
        float4* comb = reinterpret_cast<float4*>(kv_sm);
        comb[tid] = acc;                // [n][lh][lane]
        __syncthreads();
        if (tid < 128) {
            int nn = tid >> 5, hh = tid & 31;
            float4 a = comb[nn * 64 + hh];
            float4 bq = comb[nn * 64 + 32 + hh];
            a.x += bq.x; a.y += bq.y; a.z += bq.z; a.w += bq.w;
            reinterpret_cast<float4*>(g_upart + ((size_t)c * BB + b) * 512)[nn * 32 + hh] = a;
        }
    }

    // ---- last block per b finalizes ----
    __threadfence();
    __syncthreads();
    if (tid == 0) isLast = (atomicAdd(&g_cnt[b], 1) == CH - 1);
    __syncthreads();
    if (!isLast) return;
    __threadfence();

    // combine chunk stats
    if (wid < 4) {
        const int n = wid;
        float Mc = NEG_INF, Zc = 0.f;
        if (lane < CH) {
            float2 mz = g_MZ[((size_t)lane * BB + b) * NHEAD + n];
            Mc = mz.x; Zc = mz.y;
        }
        float M = warpRedMax(Mc);
        float wgt = (lane < CH) ? Zc * __expf(Mc - M) : 0.f;
        float Z = warpRedSum(wgt);
        if (lane < CH) sCoef[n * CH + lane] = __expf(Mc - M) / Z;
        if (lane == 0) { sMg[n] = M; sZinv[n] = 1.f / Z; }
    }
    __syncthreads();

    float* u_sm = kv_sm;
    float* part = kv_sm + 512;
    #pragma unroll
    for (int r = 0; r < 2; r++) {
        int idx = tid + r * 256;
        int n = idx >> 7;
        float u = 0.f;
        #pragma unroll
        for (int cc = 0; cc < CH; cc++)
            u += g_upart[((size_t)cc * BB + b) * 512 + idx] * sCoef[n * CH + cc];
        u_sm[idx] = u;
    }
    __syncthreads();

    // projection: warp wid handles i in [wid*64, wid*64+64); lane owns float4 of e
    {
        const float4* W24 = reinterpret_cast<const float4*>(g_W2);
        float4 acc = make_float4(0, 0, 0, 0);
        const int i0 = wid * 64;
        #pragma unroll 8
        for (int k = 0; k < 64; k++) {
            int i = i0 + k;
            float uv = u_sm[i];
            float4 wv = W24[(size_t)i * 32 + lane];
            acc.x += uv * wv.x; acc.y += uv * wv.y; acc.z += uv * wv.z; acc.w += uv * wv.w;
        }
        reinterpret_cast<float4*>(part)[wid * 32 + lane] = acc;
    }
    __syncthreads();

    // residual + LayerNorm
    {
        const int ts = stepp[0];
        float x = 0.f;
        if (tid < 128) {
            float p = 0.f;
            #pragma unroll
            for (int w = 0; w < 8; w++) p += part[w * 128 + tid];
            x = p + prjb[tid] + node[(size_t)b * (TT * HH) + (size_t)ts * HH + tid];
        }
        float ws = warpRedSum(x);
        if (tid < 128 && lane == 0) red[wid] = ws;
        __syncthreads();
        float mean = (red[0] + red[1] + red[2] + red[3]) * (1.f / 128.f);
        float d = x - mean;
        float wq = warpRedSum(d * d);
        if (tid < 128 && lane == 0) red2[wid] = wq;
        __syncthreads();
        if (tid < 128) {
            float var = (red2[0] + red2[1] + red2[2] + red2[3]) * (1.f / 128.f);
            outp[(size_t)b * 128 + tid] = d * rsqrtf(var + 1e-6f) * gamma[tid] + beta[tid];
        }
    }

    // slf_attn for the whole row b
    {
        const float* Sb = g_S + (size_t)b * NHEAD * LL;
        for (int l = tid; l < LL; l += 256) {
            float s = __expf(Sb[0 * LL + l] - sMg[0]) * sZinv[0]
                    + __expf(Sb[1 * LL + l] - sMg[1]) * sZinv[1]
                    + __expf(Sb[2 * LL + l] - sMg[2]) * sZinv[2]
                    + __expf(Sb[3 * LL + l] - sMg[3]) * sZinv[3];
            outp[BB * HH + (size_t)b * LL + l] = s;
        }
        if (tid == 0) g_cnt[b] = 0;   // reset for next graph replay
    }
}

extern "C" void kernel_launch(void* const* d_in, const int* in_sizes, int n_in,
                              void* d_out, int out_size)
{
    const float* node  = (const float*)d_in[0];
    const float* neigh = (const float*)d_in[1];
    const void*  mask  = d_in[2];
    const int*   step  = (const int*)d_in[3];
    const float* wqs   = (const float*)d_in[4];
    const float* wks   = (const float*)d_in[5];
    const float* wvs   = (const float*)d_in[6];
    const float* prjw  = (const float*)d_in[7];
    const float* prjb  = (const float*)d_in[8];
    const float* gamma = (const float*)d_in[9];
    const float* beta  = (const float*)d_in[10];
    float* outp = (float*)d_out;

    prep_kernel<<<132, 256>>>(node, wqs, wks, wvs, prjw,
                              (const unsigned int*)mask, step);
    mega2_kernel<<<dim3(BB, CH), 256>>>(node, neigh, mask, prjb, gamma, beta,
                                        step, outp);
}